// round 2
// baseline (speedup 1.0000x reference)
#include <cuda_runtime.h>
#include <math.h>

// Problem constants
#define BATCH   4
#define SEQLEN  2048
#define DMODEL  1024
#define NHEAD   16
#define HEADDIM 64
#define MROWS   (BATCH * SEQLEN)   // 8192

// Scratch (device globals: no allocation allowed in kernel_launch)
__device__ float g_q[(size_t)BATCH * NHEAD * SEQLEN * HEADDIM];    // [B,H,L,hd]
__device__ float g_k[(size_t)BATCH * NHEAD * SEQLEN * HEADDIM];
__device__ float g_v[(size_t)BATCH * NHEAD * SEQLEN * HEADDIM];
__device__ float g_attn[(size_t)MROWS * DMODEL];                   // [B,L,H*hd]

// ---------------------------------------------------------------------------
// GEMM: C[m,n] = sum_k A[m,k] * W[n,k] + bias[n]
// A: [8192,1024] row-major (K contiguous), W: [1024,1024] row-major (K contiguous)
// sel: 0/1/2 -> write q/k/v scratch in [B,H,L,hd] layout
//      3     -> A = g_attn, write C row-major [M, DMODEL]
// Tile: BM=128, BN=128, BK=16, 256 threads, 8x8 per thread.
// ---------------------------------------------------------------------------
__global__ __launch_bounds__(256) void gemm_nt(const float* __restrict__ A_in,
                                               const float* __restrict__ W,
                                               const float* __restrict__ bias,
                                               float* __restrict__ C_out,
                                               int sel)
{
    const int K = DMODEL;
    __shared__ float As[16][128];
    __shared__ float Bs[16][128];

    const float* A = (sel == 3) ? g_attn : A_in;
    float* C;
    if (sel == 0)      C = g_q;
    else if (sel == 1) C = g_k;
    else if (sel == 2) C = g_v;
    else               C = C_out;

    const int tid = threadIdx.x;
    const int m0 = blockIdx.y * 128;
    const int n0 = blockIdx.x * 128;
    const int ty = tid >> 4;     // 0..15
    const int tx = tid & 15;     // 0..15

    float acc[8][8];
#pragma unroll
    for (int i = 0; i < 8; i++)
#pragma unroll
        for (int j = 0; j < 8; j++) acc[i][j] = 0.0f;

    const float* Aptr = A + (size_t)m0 * K;
    const float* Wptr = W + (size_t)n0 * K;

    for (int kt = 0; kt < K; kt += 16) {
        // Load 128x16 tiles of A and W, store transposed ([k][m] / [k][n])
#pragma unroll
        for (int i = 0; i < 2; i++) {
            int idx = tid + i * 256;           // 0..511
            int row = idx >> 2;                // 0..127
            int cv  = (idx & 3) * 4;           // 0,4,8,12
            float4 av = *reinterpret_cast<const float4*>(Aptr + (size_t)row * K + kt + cv);
            As[cv + 0][row] = av.x; As[cv + 1][row] = av.y;
            As[cv + 2][row] = av.z; As[cv + 3][row] = av.w;
            float4 bv = *reinterpret_cast<const float4*>(Wptr + (size_t)row * K + kt + cv);
            Bs[cv + 0][row] = bv.x; Bs[cv + 1][row] = bv.y;
            Bs[cv + 2][row] = bv.z; Bs[cv + 3][row] = bv.w;
        }
        __syncthreads();

#pragma unroll
        for (int k = 0; k < 16; k++) {
            float a[8], b[8];
            *(float4*)&a[0] = *reinterpret_cast<const float4*>(&As[k][ty * 8]);
            *(float4*)&a[4] = *reinterpret_cast<const float4*>(&As[k][ty * 8 + 4]);
            *(float4*)&b[0] = *reinterpret_cast<const float4*>(&Bs[k][tx * 8]);
            *(float4*)&b[4] = *reinterpret_cast<const float4*>(&Bs[k][tx * 8 + 4]);
#pragma unroll
            for (int i = 0; i < 8; i++)
#pragma unroll
                for (int j = 0; j < 8; j++)
                    acc[i][j] += a[i] * b[j];
        }
        __syncthreads();
    }

    // Epilogue
    float bn[8];
#pragma unroll
    for (int j = 0; j < 8; j++) bn[j] = bias[n0 + tx * 8 + j];

#pragma unroll
    for (int i = 0; i < 8; i++) {
        int m = m0 + ty * 8 + i;
#pragma unroll
        for (int j = 0; j < 8; j++) {
            int n = n0 + tx * 8 + j;
            float val = acc[i][j] + bn[j];
            if (sel <= 2) {
                int b_ = m >> 11;       // / SEQLEN
                int l_ = m & 2047;
                int h_ = n >> 6;        // / HEADDIM
                int d_ = n & 63;
                C[(((size_t)(b_ * NHEAD + h_)) * SEQLEN + l_) * HEADDIM + d_] = val;
            } else {
                C[(size_t)m * DMODEL + n] = val;
            }
        }
    }
}

// ---------------------------------------------------------------------------
// Flash-style attention with fused RoPE.
// Grid: (L/64, B*H). Block: 256 threads.
// Each block: q-tile of 64 rows for one (b,h); loop over 32 K/V tiles of 64.
// Thread (ty,tx) 16x16 grid owns 4 rows x 4 cols of S and of O.
// ---------------------------------------------------------------------------
__global__ __launch_bounds__(256) void attn_kernel()
{
    __shared__ float Qt[64][64];   // [d][r], pre-scaled by 1/8 and RoPE'd
    __shared__ float KPt[64][64];  // K as [d][c]; reused as P^T [c][r]
    __shared__ float Vs[64][64];   // [c][d]

    const int tid = threadIdx.x;
    const int bh = blockIdx.y;                 // b*NHEAD + h
    const int b_ = bh >> 4;
    const int h_ = bh & 15;
    const float* Qg = g_q + (size_t)bh * SEQLEN * HEADDIM;
    const float* Kg = g_k + (size_t)bh * SEQLEN * HEADDIM;
    const float* Vg = g_v + (size_t)bh * SEQLEN * HEADDIM;
    const int q0 = blockIdx.x * 64;

    const int ty = tid >> 4, tx = tid & 15;
    const int r0 = ty * 4, d0 = tx * 4;

    // RoPE inv_freq for this thread's 8 (r,j) pairs: j = (tid + 256p) & 31
    float invf[8];
#pragma unroll
    for (int p = 0; p < 8; p++) {
        int j = (tid + p * 256) & 31;
        invf[p] = __expf(-(float)j * (9.210340371976184f / 32.0f)); // ln(10000)
    }

    // ---- Load Q tile transposed ----
#pragma unroll
    for (int i = 0; i < 4; i++) {
        int idx = tid + i * 256;        // 0..1023 float4 slots
        int r = idx >> 4;               // 0..63
        int cv = (idx & 15) * 4;        // 0..60
        float4 v = *reinterpret_cast<const float4*>(Qg + (size_t)(q0 + r) * HEADDIM + cv);
        Qt[cv + 0][r] = v.x; Qt[cv + 1][r] = v.y;
        Qt[cv + 2][r] = v.z; Qt[cv + 3][r] = v.w;
    }
    __syncthreads();
    // ---- RoPE Q in place, fold in softmax scale 1/sqrt(64) ----
#pragma unroll
    for (int p = 0; p < 8; p++) {
        int pid = tid + p * 256;        // 0..2047
        int r = pid >> 5;               // 0..63
        int j = pid & 31;               // 0..31
        float ang = (float)(q0 + r) * invf[p];
        float sn, cs; sincosf(ang, &sn, &cs);
        float x1 = Qt[j][r], x2 = Qt[j + 32][r];
        Qt[j][r]      = (x1 * cs - x2 * sn) * 0.125f;
        Qt[j + 32][r] = (x2 * cs + x1 * sn) * 0.125f;
    }

    float m_i[4], l_i[4], o[4][4];
#pragma unroll
    for (int i = 0; i < 4; i++) {
        m_i[i] = -INFINITY; l_i[i] = 0.0f;
#pragma unroll
        for (int j = 0; j < 4; j++) o[i][j] = 0.0f;
    }

    for (int kk = 0; kk < 32; kk++) {
        const int kv0 = kk * 64;
        __syncthreads();   // Qt rope done (kk=0); prior P/V reads done (kk>0)

        // ---- Load K (transposed) and V tiles ----
#pragma unroll
        for (int i = 0; i < 4; i++) {
            int idx = tid + i * 256;
            int r = idx >> 4;
            int cv = (idx & 15) * 4;
            float4 kv = *reinterpret_cast<const float4*>(Kg + (size_t)(kv0 + r) * HEADDIM + cv);
            KPt[cv + 0][r] = kv.x; KPt[cv + 1][r] = kv.y;
            KPt[cv + 2][r] = kv.z; KPt[cv + 3][r] = kv.w;
            float4 vv = *reinterpret_cast<const float4*>(Vg + (size_t)(kv0 + r) * HEADDIM + cv);
            *(float4*)&Vs[r][cv] = vv;
        }
        __syncthreads();
        // ---- RoPE K in place ----
#pragma unroll
        for (int p = 0; p < 8; p++) {
            int pid = tid + p * 256;
            int r = pid >> 5;
            int j = pid & 31;
            float ang = (float)(kv0 + r) * invf[p];
            float sn, cs; sincosf(ang, &sn, &cs);
            float x1 = KPt[j][r], x2 = KPt[j + 32][r];
            KPt[j][r]      = x1 * cs - x2 * sn;
            KPt[j + 32][r] = x2 * cs + x1 * sn;
        }
        __syncthreads();

        // ---- S = (Q/8) . K^T : 4x4 per thread over d=64 ----
        float s[4][4];
#pragma unroll
        for (int i = 0; i < 4; i++)
#pragma unroll
            for (int j = 0; j < 4; j++) s[i][j] = 0.0f;

#pragma unroll 8
        for (int d = 0; d < 64; d++) {
            float a[4], bb[4];
            *(float4*)a  = *reinterpret_cast<const float4*>(&Qt[d][r0]);
            *(float4*)bb = *reinterpret_cast<const float4*>(&KPt[d][d0]);
#pragma unroll
            for (int i = 0; i < 4; i++)
#pragma unroll
                for (int j = 0; j < 4; j++)
                    s[i][j] += a[i] * bb[j];
        }

        // ---- Online softmax (row reductions across the 16 tx lanes) ----
#pragma unroll
        for (int i = 0; i < 4; i++) {
            float mx = fmaxf(fmaxf(s[i][0], s[i][1]), fmaxf(s[i][2], s[i][3]));
            mx = fmaxf(mx, __shfl_xor_sync(0xffffffffu, mx, 1));
            mx = fmaxf(mx, __shfl_xor_sync(0xffffffffu, mx, 2));
            mx = fmaxf(mx, __shfl_xor_sync(0xffffffffu, mx, 4));
            mx = fmaxf(mx, __shfl_xor_sync(0xffffffffu, mx, 8));
            float mnew = fmaxf(m_i[i], mx);
            float corr = __expf(m_i[i] - mnew);
            float rs = 0.0f;
#pragma unroll
            for (int j = 0; j < 4; j++) {
                float p = __expf(s[i][j] - mnew);
                s[i][j] = p;
                rs += p;
            }
            rs += __shfl_xor_sync(0xffffffffu, rs, 1);
            rs += __shfl_xor_sync(0xffffffffu, rs, 2);
            rs += __shfl_xor_sync(0xffffffffu, rs, 4);
            rs += __shfl_xor_sync(0xffffffffu, rs, 8);
            l_i[i] = l_i[i] * corr + rs;
            m_i[i] = mnew;
#pragma unroll
            for (int j = 0; j < 4; j++) o[i][j] *= corr;
        }

        __syncthreads();   // all S-compute reads of KPt finished
        // ---- P^T into KPt: thread's s[i][j] = P[r0+i][c0+j], c0 == d0 ----
#pragma unroll
        for (int i = 0; i < 4; i++)
#pragma unroll
            for (int j = 0; j < 4; j++)
                KPt[d0 + j][r0 + i] = s[i][j];
        __syncthreads();

        // ---- O += P . V ----
#pragma unroll 8
        for (int c = 0; c < 64; c++) {
            float p[4], vv[4];
            *(float4*)p  = *reinterpret_cast<const float4*>(&KPt[c][r0]);
            *(float4*)vv = *reinterpret_cast<const float4*>(&Vs[c][d0]);
#pragma unroll
            for (int i = 0; i < 4; i++)
#pragma unroll
                for (int j = 0; j < 4; j++)
                    o[i][j] += p[i] * vv[j];
        }
    }

    // ---- Epilogue: normalize, write [B,L,H*hd] ----
#pragma unroll
    for (int i = 0; i < 4; i++) {
        float inv = 1.0f / l_i[i];
        int row = q0 + r0 + i;
        float4 res;
        res.x = o[i][0] * inv;
        res.y = o[i][1] * inv;
        res.z = o[i][2] * inv;
        res.w = o[i][3] * inv;
        *(float4*)(g_attn + ((size_t)(b_ * SEQLEN + row) * NHEAD + h_) * HEADDIM + d0) = res;
    }
}

// ---------------------------------------------------------------------------
extern "C" void kernel_launch(void* const* d_in, const int* in_sizes, int n_in,
                              void* d_out, int out_size)
{
    const float* x  = (const float*)d_in[0];
    const float* Wq = (const float*)d_in[1];
    const float* bq = (const float*)d_in[2];
    const float* Wk = (const float*)d_in[3];
    const float* bk = (const float*)d_in[4];
    const float* Wv = (const float*)d_in[5];
    const float* bv = (const float*)d_in[6];
    const float* Wo = (const float*)d_in[7];
    const float* bo = (const float*)d_in[8];
    float* out = (float*)d_out;

    dim3 ggrid(DMODEL / 128, MROWS / 128);   // (8, 64)
    gemm_nt<<<ggrid, 256>>>(x, Wq, bq, nullptr, 0);
    gemm_nt<<<ggrid, 256>>>(x, Wk, bk, nullptr, 1);
    gemm_nt<<<ggrid, 256>>>(x, Wv, bv, nullptr, 2);

    attn_kernel<<<dim3(SEQLEN / 64, BATCH * NHEAD), 256>>>();

    gemm_nt<<<ggrid, 256>>>(nullptr, Wo, bo, out, 3);
}

// round 4
// speedup vs baseline: 2.3954x; 2.3954x over previous
#include <cuda_runtime.h>
#include <math.h>
#include <stdint.h>

// Problem constants
#define BATCH   4
#define SEQLEN  2048
#define DMODEL  1024
#define NHEAD   16
#define HEADDIM 64
#define MROWS   (BATCH * SEQLEN)   // 8192

// Scratch (device globals: no allocation allowed in kernel_launch)
__device__ float g_q[(size_t)BATCH * NHEAD * SEQLEN * HEADDIM];    // [B,H,L,hd]
__device__ float g_k[(size_t)BATCH * NHEAD * SEQLEN * HEADDIM];
__device__ float g_v[(size_t)BATCH * NHEAD * SEQLEN * HEADDIM];
__device__ float g_attn[(size_t)MROWS * DMODEL];                   // [B,L,H*hd]

// ---------------------------------------------------------------------------
// GEMM: C[m,n] = sum_k A[m,k] * W[n,k] + bias[n]   (unchanged from round 2)
// ---------------------------------------------------------------------------
__global__ __launch_bounds__(256) void gemm_nt(const float* __restrict__ A_in,
                                               const float* __restrict__ W,
                                               const float* __restrict__ bias,
                                               float* __restrict__ C_out,
                                               int sel)
{
    const int K = DMODEL;
    __shared__ float As[16][128];
    __shared__ float Bs[16][128];

    const float* A = (sel == 3) ? g_attn : A_in;
    float* C;
    if (sel == 0)      C = g_q;
    else if (sel == 1) C = g_k;
    else if (sel == 2) C = g_v;
    else               C = C_out;

    const int tid = threadIdx.x;
    const int m0 = blockIdx.y * 128;
    const int n0 = blockIdx.x * 128;
    const int ty = tid >> 4;
    const int tx = tid & 15;

    float acc[8][8];
#pragma unroll
    for (int i = 0; i < 8; i++)
#pragma unroll
        for (int j = 0; j < 8; j++) acc[i][j] = 0.0f;

    const float* Aptr = A + (size_t)m0 * K;
    const float* Wptr = W + (size_t)n0 * K;

    for (int kt = 0; kt < K; kt += 16) {
#pragma unroll
        for (int i = 0; i < 2; i++) {
            int idx = tid + i * 256;
            int row = idx >> 2;
            int cv  = (idx & 3) * 4;
            float4 av = *reinterpret_cast<const float4*>(Aptr + (size_t)row * K + kt + cv);
            As[cv + 0][row] = av.x; As[cv + 1][row] = av.y;
            As[cv + 2][row] = av.z; As[cv + 3][row] = av.w;
            float4 bv = *reinterpret_cast<const float4*>(Wptr + (size_t)row * K + kt + cv);
            Bs[cv + 0][row] = bv.x; Bs[cv + 1][row] = bv.y;
            Bs[cv + 2][row] = bv.z; Bs[cv + 3][row] = bv.w;
        }
        __syncthreads();

#pragma unroll
        for (int k = 0; k < 16; k++) {
            float a[8], b[8];
            *(float4*)&a[0] = *reinterpret_cast<const float4*>(&As[k][ty * 8]);
            *(float4*)&a[4] = *reinterpret_cast<const float4*>(&As[k][ty * 8 + 4]);
            *(float4*)&b[0] = *reinterpret_cast<const float4*>(&Bs[k][tx * 8]);
            *(float4*)&b[4] = *reinterpret_cast<const float4*>(&Bs[k][tx * 8 + 4]);
#pragma unroll
            for (int i = 0; i < 8; i++)
#pragma unroll
                for (int j = 0; j < 8; j++)
                    acc[i][j] += a[i] * b[j];
        }
        __syncthreads();
    }

    float bn[8];
#pragma unroll
    for (int j = 0; j < 8; j++) bn[j] = bias[n0 + tx * 8 + j];

#pragma unroll
    for (int i = 0; i < 8; i++) {
        int m = m0 + ty * 8 + i;
#pragma unroll
        for (int j = 0; j < 8; j++) {
            int n = n0 + tx * 8 + j;
            float val = acc[i][j] + bn[j];
            if (sel <= 2) {
                int b_ = m >> 11;
                int l_ = m & 2047;
                int h_ = n >> 6;
                int d_ = n & 63;
                C[(((size_t)(b_ * NHEAD + h_)) * SEQLEN + l_) * HEADDIM + d_] = val;
            } else {
                C[(size_t)m * DMODEL + n] = val;
            }
        }
    }
}

// ---------------------------------------------------------------------------
// TF32 mma helpers
// ---------------------------------------------------------------------------
__device__ __forceinline__ uint32_t f2tf32(float f) {
    uint32_t u;
    asm("cvt.rna.tf32.f32 %0, %1;" : "=r"(u) : "f"(f));
    return u;
}

__device__ __forceinline__ void mma_tf32(float* d, const uint32_t* a,
                                         uint32_t b0, uint32_t b1) {
    asm volatile(
        "mma.sync.aligned.m16n8k8.row.col.f32.tf32.tf32.f32 "
        "{%0,%1,%2,%3}, {%4,%5,%6,%7}, {%8,%9}, {%0,%1,%2,%3};\n"
        : "+f"(d[0]), "+f"(d[1]), "+f"(d[2]), "+f"(d[3])
        : "r"(a[0]), "r"(a[1]), "r"(a[2]), "r"(a[3]), "r"(b0), "r"(b1));
}

// ---------------------------------------------------------------------------
// Flash attention with fused RoPE, tensor-core (tf32) S and P.V.
// Grid: (L/128, B*H). Block: 128 threads (4 warps).
// Warp w owns q-rows [w*32, w*32+32): 2 m16 fragments. kv tiles of 64.
// ---------------------------------------------------------------------------
__global__ __launch_bounds__(128) void attn_mma_kernel()
{
    // Union: Qs[128][68] staging overlaps (Ks[64][68], Vs[64][72])
    __shared__ float smem_all[64 * 68 + 64 * 72];   // 35840 B
    float (*Ks)[68] = (float(*)[68])smem_all;
    float (*Vs)[72] = (float(*)[72])(smem_all + 64 * 68);
    float (*Qs)[68] = (float(*)[68])smem_all;       // 128*68 = 8704 <= 8960

    const int tid  = threadIdx.x;
    const int w    = tid >> 5;
    const int lane = tid & 31;
    const int g    = lane >> 2;      // group (row within frag / n within frag)
    const int q    = lane & 3;       // quad lane (col within frag / k within frag)

    const int bh = blockIdx.y;
    const int b_ = bh >> 4;
    const int h_ = bh & 15;
    const int q0 = blockIdx.x * 128;

    const float* Qg = g_q + (size_t)bh * SEQLEN * HEADDIM;
    const float* Kg = g_k + (size_t)bh * SEQLEN * HEADDIM;
    const float* Vg = g_v + (size_t)bh * SEQLEN * HEADDIM;

    // RoPE frequency for this thread's fixed j = tid & 31 (stride-128 loops keep j constant)
    const int jr = tid & 31;
    const float invf = __expf(-(float)jr * (9.210340371976184f / 32.0f)); // 10000^(-j/32)

    // ---- Load Q tile [128][64] ----
#pragma unroll
    for (int i = 0; i < 16; i++) {
        int idx = tid + i * 128;
        int r = idx >> 4;
        int cv = (idx & 15) * 4;
        float4 v = *reinterpret_cast<const float4*>(Qg + (size_t)(q0 + r) * HEADDIM + cv);
        Qs[r][cv + 0] = v.x; Qs[r][cv + 1] = v.y;
        Qs[r][cv + 2] = v.z; Qs[r][cv + 3] = v.w;
    }
    __syncthreads();

    // ---- RoPE Q in place + fold softmax scale 1/8 ----
#pragma unroll
    for (int i = 0; i < 32; i++) {
        int r = (tid >> 5) + i * 4;          // 0..127
        float sn, cs;
        sincosf((float)(q0 + r) * invf, &sn, &cs);
        float x1 = Qs[r][jr], x2 = Qs[r][jr + 32];
        Qs[r][jr]      = (x1 * cs - x2 * sn) * 0.125f;
        Qs[r][jr + 32] = (x2 * cs + x1 * sn) * 0.125f;
    }
    __syncthreads();

    // ---- Extract Q A-fragments (persist in registers for whole kv loop) ----
    uint32_t aq[2][8][4];
#pragma unroll
    for (int t = 0; t < 2; t++) {
        int row0 = w * 32 + t * 16 + g;
#pragma unroll
        for (int kc = 0; kc < 8; kc++) {
            int c0 = kc * 8 + q;
            aq[t][kc][0] = f2tf32(Qs[row0][c0]);
            aq[t][kc][1] = f2tf32(Qs[row0 + 8][c0]);
            aq[t][kc][2] = f2tf32(Qs[row0][c0 + 4]);
            aq[t][kc][3] = f2tf32(Qs[row0 + 8][c0 + 4]);
        }
    }

    // Online softmax state (per lane: rows g and g+8 of each m-frag)
    float o[2][8][4];
    float mA[2], mB[2], lA[2], lB[2];
#pragma unroll
    for (int t = 0; t < 2; t++) {
        mA[t] = -INFINITY; mB[t] = -INFINITY; lA[t] = 0.0f; lB[t] = 0.0f;
#pragma unroll
        for (int n = 0; n < 8; n++)
#pragma unroll
            for (int c = 0; c < 4; c++) o[t][n][c] = 0.0f;
    }

    for (int kk = 0; kk < 32; kk++) {
        const int kv0 = kk * 64;
        __syncthreads();   // kk=0: Q frags extracted; kk>0: prior mma reads done

        // ---- Load K (raw) and V (tf32-converted) tiles ----
#pragma unroll
        for (int i = 0; i < 8; i++) {
            int idx = tid + i * 128;
            int r = idx >> 4;
            int cv = (idx & 15) * 4;
            float4 kv = *reinterpret_cast<const float4*>(Kg + (size_t)(kv0 + r) * HEADDIM + cv);
            Ks[r][cv + 0] = kv.x; Ks[r][cv + 1] = kv.y;
            Ks[r][cv + 2] = kv.z; Ks[r][cv + 3] = kv.w;
            float4 vv = *reinterpret_cast<const float4*>(Vg + (size_t)(kv0 + r) * HEADDIM + cv);
            Vs[r][cv + 0] = __uint_as_float(f2tf32(vv.x));
            Vs[r][cv + 1] = __uint_as_float(f2tf32(vv.y));
            Vs[r][cv + 2] = __uint_as_float(f2tf32(vv.z));
            Vs[r][cv + 3] = __uint_as_float(f2tf32(vv.w));
        }
        __syncthreads();

        // ---- RoPE K in place (+ tf32 convert) ----
#pragma unroll
        for (int i = 0; i < 16; i++) {
            int r = (tid >> 5) + i * 4;      // 0..63
            float sn, cs;
            sincosf((float)(kv0 + r) * invf, &sn, &cs);
            float x1 = Ks[r][jr], x2 = Ks[r][jr + 32];
            Ks[r][jr]      = __uint_as_float(f2tf32(x1 * cs - x2 * sn));
            Ks[r][jr + 32] = __uint_as_float(f2tf32(x2 * cs + x1 * sn));
        }
        __syncthreads();

        // ---- S = Q . K^T  (m16n8k8 tf32) ----
        float s[2][8][4];
#pragma unroll
        for (int t = 0; t < 2; t++)
#pragma unroll
            for (int n = 0; n < 8; n++)
#pragma unroll
                for (int c = 0; c < 4; c++) s[t][n][c] = 0.0f;

#pragma unroll
        for (int n = 0; n < 8; n++) {
#pragma unroll
            for (int kc = 0; kc < 8; kc++) {
                uint32_t b0 = __float_as_uint(Ks[n * 8 + g][kc * 8 + q]);
                uint32_t b1 = __float_as_uint(Ks[n * 8 + g][kc * 8 + q + 4]);
                mma_tf32(s[0][n], aq[0][kc], b0, b1);
                mma_tf32(s[1][n], aq[1][kc], b0, b1);
            }
        }

        // ---- Online softmax ----
#pragma unroll
        for (int t = 0; t < 2; t++) {
            float mxA = -1e30f, mxB = -1e30f;
#pragma unroll
            for (int n = 0; n < 8; n++) {
                mxA = fmaxf(mxA, fmaxf(s[t][n][0], s[t][n][1]));
                mxB = fmaxf(mxB, fmaxf(s[t][n][2], s[t][n][3]));
            }
            mxA = fmaxf(mxA, __shfl_xor_sync(0xffffffffu, mxA, 1));
            mxA = fmaxf(mxA, __shfl_xor_sync(0xffffffffu, mxA, 2));
            mxB = fmaxf(mxB, __shfl_xor_sync(0xffffffffu, mxB, 1));
            mxB = fmaxf(mxB, __shfl_xor_sync(0xffffffffu, mxB, 2));
            float mnA = fmaxf(mA[t], mxA);
            float mnB = fmaxf(mB[t], mxB);
            float cA = __expf(mA[t] - mnA);
            float cB = __expf(mB[t] - mnB);
            float rsA = 0.0f, rsB = 0.0f;
#pragma unroll
            for (int n = 0; n < 8; n++) {
                s[t][n][0] = __expf(s[t][n][0] - mnA); rsA += s[t][n][0];
                s[t][n][1] = __expf(s[t][n][1] - mnA); rsA += s[t][n][1];
                s[t][n][2] = __expf(s[t][n][2] - mnB); rsB += s[t][n][2];
                s[t][n][3] = __expf(s[t][n][3] - mnB); rsB += s[t][n][3];
                o[t][n][0] *= cA; o[t][n][1] *= cA;
                o[t][n][2] *= cB; o[t][n][3] *= cB;
            }
            rsA += __shfl_xor_sync(0xffffffffu, rsA, 1);
            rsA += __shfl_xor_sync(0xffffffffu, rsA, 2);
            rsB += __shfl_xor_sync(0xffffffffu, rsB, 1);
            rsB += __shfl_xor_sync(0xffffffffu, rsB, 2);
            lA[t] = lA[t] * cA + rsA; mA[t] = mnA;
            lB[t] = lB[t] * cB + rsB; mB[t] = mnB;
        }

        // ---- O += P . V : build P A-frags from S accum layout via shfl ----
        const int src0 = (g << 2) + (q >> 1);
        const int src1 = src0 + 2;
        const bool odd = (q & 1);
#pragma unroll
        for (int kc = 0; kc < 8; kc++) {
            uint32_t ap[2][4];
#pragma unroll
            for (int t = 0; t < 2; t++) {
                float v00 = __shfl_sync(0xffffffffu, s[t][kc][0], src0);
                float v01 = __shfl_sync(0xffffffffu, s[t][kc][1], src0);
                float v02 = __shfl_sync(0xffffffffu, s[t][kc][2], src0);
                float v03 = __shfl_sync(0xffffffffu, s[t][kc][3], src0);
                float v10 = __shfl_sync(0xffffffffu, s[t][kc][0], src1);
                float v11 = __shfl_sync(0xffffffffu, s[t][kc][1], src1);
                float v12 = __shfl_sync(0xffffffffu, s[t][kc][2], src1);
                float v13 = __shfl_sync(0xffffffffu, s[t][kc][3], src1);
                ap[t][0] = f2tf32(odd ? v01 : v00);
                ap[t][1] = f2tf32(odd ? v03 : v02);
                ap[t][2] = f2tf32(odd ? v11 : v10);
                ap[t][3] = f2tf32(odd ? v13 : v12);
            }
#pragma unroll
            for (int n = 0; n < 8; n++) {
                uint32_t b0 = __float_as_uint(Vs[kc * 8 + q][n * 8 + g]);
                uint32_t b1 = __float_as_uint(Vs[kc * 8 + q + 4][n * 8 + g]);
                mma_tf32(o[0][n], ap[0], b0, b1);
                mma_tf32(o[1][n], ap[1], b0, b1);
            }
        }
    }

    // ---- Epilogue: normalize, write [B,L,H*hd] ----
#pragma unroll
    for (int t = 0; t < 2; t++) {
        float iA = 1.0f / lA[t];
        float iB = 1.0f / lB[t];
        int row0 = q0 + w * 32 + t * 16 + g;
#pragma unroll
        for (int n = 0; n < 8; n++) {
            int col = n * 8 + 2 * q;
            float2 r0v = make_float2(o[t][n][0] * iA, o[t][n][1] * iA);
            float2 r1v = make_float2(o[t][n][2] * iB, o[t][n][3] * iB);
            *reinterpret_cast<float2*>(
                g_attn + ((size_t)(b_ * SEQLEN + row0) * NHEAD + h_) * HEADDIM + col) = r0v;
            *reinterpret_cast<float2*>(
                g_attn + ((size_t)(b_ * SEQLEN + row0 + 8) * NHEAD + h_) * HEADDIM + col) = r1v;
        }
    }
}

// ---------------------------------------------------------------------------
extern "C" void kernel_launch(void* const* d_in, const int* in_sizes, int n_in,
                              void* d_out, int out_size)
{
    const float* x  = (const float*)d_in[0];
    const float* Wq = (const float*)d_in[1];
    const float* bq = (const float*)d_in[2];
    const float* Wk = (const float*)d_in[3];
    const float* bk = (const float*)d_in[4];
    const float* Wv = (const float*)d_in[5];
    const float* bv = (const float*)d_in[6];
    const float* Wo = (const float*)d_in[7];
    const float* bo = (const float*)d_in[8];
    float* out = (float*)d_out;

    dim3 ggrid(DMODEL / 128, MROWS / 128);   // (8, 64)
    gemm_nt<<<ggrid, 256>>>(x, Wq, bq, nullptr, 0);
    gemm_nt<<<ggrid, 256>>>(x, Wk, bk, nullptr, 1);
    gemm_nt<<<ggrid, 256>>>(x, Wv, bv, nullptr, 2);

    attn_mma_kernel<<<dim3(SEQLEN / 128, BATCH * NHEAD), 128>>>();

    gemm_nt<<<ggrid, 256>>>(nullptr, Wo, bo, out, 3);
}

// round 5
// speedup vs baseline: 4.8999x; 2.0456x over previous
#include <cuda_runtime.h>
#include <math.h>
#include <stdint.h>

// Problem constants
#define BATCH   4
#define SEQLEN  2048
#define DMODEL  1024
#define NHEAD   16
#define HEADDIM 64
#define MROWS   (BATCH * SEQLEN)   // 8192

// Scratch (device globals: no allocation allowed in kernel_launch)
__device__ float g_q[(size_t)BATCH * NHEAD * SEQLEN * HEADDIM];    // [B,H,L,hd]
__device__ float g_k[(size_t)BATCH * NHEAD * SEQLEN * HEADDIM];
__device__ float g_v[(size_t)BATCH * NHEAD * SEQLEN * HEADDIM];
__device__ float g_attn[(size_t)MROWS * DMODEL];                   // [B,L,H*hd]

// ---------------------------------------------------------------------------
// TF32 mma helpers
// ---------------------------------------------------------------------------
__device__ __forceinline__ uint32_t f2tf32(float f) {
    uint32_t u;
    asm("cvt.rna.tf32.f32 %0, %1;" : "=r"(u) : "f"(f));
    return u;
}

__device__ __forceinline__ void mma_tf32(float* d, const uint32_t* a,
                                         uint32_t b0, uint32_t b1) {
    asm volatile(
        "mma.sync.aligned.m16n8k8.row.col.f32.tf32.tf32.f32 "
        "{%0,%1,%2,%3}, {%4,%5,%6,%7}, {%8,%9}, {%0,%1,%2,%3};\n"
        : "+f"(d[0]), "+f"(d[1]), "+f"(d[2]), "+f"(d[3])
        : "r"(a[0]), "r"(a[1]), "r"(a[2]), "r"(a[3]), "r"(b0), "r"(b1));
}

// ---------------------------------------------------------------------------
// TF32 tensor-core GEMM: C[m,n] = sum_k A[m,k] * W[n,k] + bias[n]
// A: [M,K] row-major, W: [N,K] row-major (both K-contiguous).
// sel: 0/1/2 -> scatter to q/k/v scratch [B,H,L,hd]; 3 -> row-major [M,DMODEL]
// Block 128x128, BK=32, 256 threads (8 warps), warp tile 64x32.
// ---------------------------------------------------------------------------
__global__ __launch_bounds__(256) void gemm_tf32(const float* __restrict__ A_in,
                                                 const float* __restrict__ W,
                                                 const float* __restrict__ bias,
                                                 float* __restrict__ C_out,
                                                 int sel)
{
    __shared__ float As[128][36];   // tf32 bits, stride 36 -> conflict-free frags
    __shared__ float Ws[128][36];

    const int K = DMODEL;
    const float* A = (sel == 3) ? g_attn : A_in;
    float* C;
    if (sel == 0)      C = g_q;
    else if (sel == 1) C = g_k;
    else if (sel == 2) C = g_v;
    else               C = C_out;

    const int tid  = threadIdx.x;
    const int w    = tid >> 5;
    const int lane = tid & 31;
    const int g    = lane >> 2;
    const int q    = lane & 3;
    const int wm   = (w & 1) * 64;     // warp m-offset within block
    const int wn   = (w >> 1) * 32;    // warp n-offset within block

    const int m0 = blockIdx.y * 128;
    const int n0 = blockIdx.x * 128;

    const float* Aptr = A + (size_t)m0 * K;
    const float* Wptr = W + (size_t)n0 * K;

    // Global-load mapping: idx = tid + i*256 in [0,1024); row=idx>>3, c4=(idx&7)*4
    int ld_row[4], ld_c4[4];
#pragma unroll
    for (int i = 0; i < 4; i++) {
        int idx = tid + i * 256;
        ld_row[i] = idx >> 3;
        ld_c4[i]  = (idx & 7) * 4;
    }

    float acc[4][4][4];
#pragma unroll
    for (int mi = 0; mi < 4; mi++)
#pragma unroll
        for (int nj = 0; nj < 4; nj++)
#pragma unroll
            for (int c = 0; c < 4; c++) acc[mi][nj][c] = 0.0f;

    // Prefetch tile 0
    float4 pa[4], pw[4];
#pragma unroll
    for (int i = 0; i < 4; i++) {
        pa[i] = *reinterpret_cast<const float4*>(Aptr + (size_t)ld_row[i] * K + ld_c4[i]);
        pw[i] = *reinterpret_cast<const float4*>(Wptr + (size_t)ld_row[i] * K + ld_c4[i]);
    }

    for (int kt = 0; kt < K; kt += 32) {
        // Store prefetched tile (tf32-converted) to smem
#pragma unroll
        for (int i = 0; i < 4; i++) {
            float4 a = pa[i];
            float4 t;
            t.x = __uint_as_float(f2tf32(a.x));
            t.y = __uint_as_float(f2tf32(a.y));
            t.z = __uint_as_float(f2tf32(a.z));
            t.w = __uint_as_float(f2tf32(a.w));
            *reinterpret_cast<float4*>(&As[ld_row[i]][ld_c4[i]]) = t;
            float4 b = pw[i];
            t.x = __uint_as_float(f2tf32(b.x));
            t.y = __uint_as_float(f2tf32(b.y));
            t.z = __uint_as_float(f2tf32(b.z));
            t.w = __uint_as_float(f2tf32(b.w));
            *reinterpret_cast<float4*>(&Ws[ld_row[i]][ld_c4[i]]) = t;
        }
        __syncthreads();

        // Prefetch next tile
        if (kt + 32 < K) {
#pragma unroll
            for (int i = 0; i < 4; i++) {
                pa[i] = *reinterpret_cast<const float4*>(
                    Aptr + (size_t)ld_row[i] * K + kt + 32 + ld_c4[i]);
                pw[i] = *reinterpret_cast<const float4*>(
                    Wptr + (size_t)ld_row[i] * K + kt + 32 + ld_c4[i]);
            }
        }

        // Compute: 4 k-chunks of 8
#pragma unroll
        for (int kc = 0; kc < 4; kc++) {
            const int k0 = kc * 8;
            uint32_t a[4][4];
#pragma unroll
            for (int mi = 0; mi < 4; mi++) {
                int r = wm + mi * 16;
                a[mi][0] = __float_as_uint(As[r + g][k0 + q]);
                a[mi][1] = __float_as_uint(As[r + 8 + g][k0 + q]);
                a[mi][2] = __float_as_uint(As[r + g][k0 + q + 4]);
                a[mi][3] = __float_as_uint(As[r + 8 + g][k0 + q + 4]);
            }
            uint32_t b[4][2];
#pragma unroll
            for (int nj = 0; nj < 4; nj++) {
                int bn = wn + nj * 8;
                b[nj][0] = __float_as_uint(Ws[bn + g][k0 + q]);
                b[nj][1] = __float_as_uint(Ws[bn + g][k0 + q + 4]);
            }
#pragma unroll
            for (int mi = 0; mi < 4; mi++)
#pragma unroll
                for (int nj = 0; nj < 4; nj++)
                    mma_tf32(acc[mi][nj], a[mi], b[nj][0], b[nj][1]);
        }
        __syncthreads();
    }

    // ---- Epilogue: bias + store ----
#pragma unroll
    for (int nj = 0; nj < 4; nj++) {
        int cn = n0 + wn + nj * 8 + 2 * q;
        float b0 = bias[cn];
        float b1 = bias[cn + 1];
#pragma unroll
        for (int mi = 0; mi < 4; mi++) {
            int mr0 = m0 + wm + mi * 16 + g;
            int mr1 = mr0 + 8;
            float2 v0 = make_float2(acc[mi][nj][0] + b0, acc[mi][nj][1] + b1);
            float2 v1 = make_float2(acc[mi][nj][2] + b0, acc[mi][nj][3] + b1);
            if (sel <= 2) {
                int h_ = cn >> 6;
                int d_ = cn & 63;
                int b0_ = mr0 >> 11, l0_ = mr0 & 2047;
                int b1_ = mr1 >> 11, l1_ = mr1 & 2047;
                *reinterpret_cast<float2*>(
                    C + (((size_t)(b0_ * NHEAD + h_)) * SEQLEN + l0_) * HEADDIM + d_) = v0;
                *reinterpret_cast<float2*>(
                    C + (((size_t)(b1_ * NHEAD + h_)) * SEQLEN + l1_) * HEADDIM + d_) = v1;
            } else {
                *reinterpret_cast<float2*>(C + (size_t)mr0 * DMODEL + cn) = v0;
                *reinterpret_cast<float2*>(C + (size_t)mr1 * DMODEL + cn) = v1;
            }
        }
    }
}

// ---------------------------------------------------------------------------
// Flash attention with fused RoPE, tensor-core (tf32) S and P.V. (unchanged)
// Grid: (L/128, B*H). Block: 128 threads (4 warps).
// ---------------------------------------------------------------------------
__global__ __launch_bounds__(128) void attn_mma_kernel()
{
    __shared__ float smem_all[64 * 68 + 64 * 72];   // 35840 B
    float (*Ks)[68] = (float(*)[68])smem_all;
    float (*Vs)[72] = (float(*)[72])(smem_all + 64 * 68);
    float (*Qs)[68] = (float(*)[68])smem_all;

    const int tid  = threadIdx.x;
    const int w    = tid >> 5;
    const int lane = tid & 31;
    const int g    = lane >> 2;
    const int q    = lane & 3;

    const int bh = blockIdx.y;
    const int b_ = bh >> 4;
    const int h_ = bh & 15;
    const int q0 = blockIdx.x * 128;

    const float* Qg = g_q + (size_t)bh * SEQLEN * HEADDIM;
    const float* Kg = g_k + (size_t)bh * SEQLEN * HEADDIM;
    const float* Vg = g_v + (size_t)bh * SEQLEN * HEADDIM;

    const int jr = tid & 31;
    const float invf = __expf(-(float)jr * (9.210340371976184f / 32.0f));

    // ---- Load Q tile [128][64] ----
#pragma unroll
    for (int i = 0; i < 16; i++) {
        int idx = tid + i * 128;
        int r = idx >> 4;
        int cv = (idx & 15) * 4;
        float4 v = *reinterpret_cast<const float4*>(Qg + (size_t)(q0 + r) * HEADDIM + cv);
        Qs[r][cv + 0] = v.x; Qs[r][cv + 1] = v.y;
        Qs[r][cv + 2] = v.z; Qs[r][cv + 3] = v.w;
    }
    __syncthreads();

    // ---- RoPE Q in place + fold softmax scale 1/8 ----
#pragma unroll
    for (int i = 0; i < 32; i++) {
        int r = (tid >> 5) + i * 4;
        float sn, cs;
        sincosf((float)(q0 + r) * invf, &sn, &cs);
        float x1 = Qs[r][jr], x2 = Qs[r][jr + 32];
        Qs[r][jr]      = (x1 * cs - x2 * sn) * 0.125f;
        Qs[r][jr + 32] = (x2 * cs + x1 * sn) * 0.125f;
    }
    __syncthreads();

    // ---- Extract Q A-fragments ----
    uint32_t aq[2][8][4];
#pragma unroll
    for (int t = 0; t < 2; t++) {
        int row0 = w * 32 + t * 16 + g;
#pragma unroll
        for (int kc = 0; kc < 8; kc++) {
            int c0 = kc * 8 + q;
            aq[t][kc][0] = f2tf32(Qs[row0][c0]);
            aq[t][kc][1] = f2tf32(Qs[row0 + 8][c0]);
            aq[t][kc][2] = f2tf32(Qs[row0][c0 + 4]);
            aq[t][kc][3] = f2tf32(Qs[row0 + 8][c0 + 4]);
        }
    }

    float o[2][8][4];
    float mA[2], mB[2], lA[2], lB[2];
#pragma unroll
    for (int t = 0; t < 2; t++) {
        mA[t] = -INFINITY; mB[t] = -INFINITY; lA[t] = 0.0f; lB[t] = 0.0f;
#pragma unroll
        for (int n = 0; n < 8; n++)
#pragma unroll
            for (int c = 0; c < 4; c++) o[t][n][c] = 0.0f;
    }

    for (int kk = 0; kk < 32; kk++) {
        const int kv0 = kk * 64;
        __syncthreads();

#pragma unroll
        for (int i = 0; i < 8; i++) {
            int idx = tid + i * 128;
            int r = idx >> 4;
            int cv = (idx & 15) * 4;
            float4 kv = *reinterpret_cast<const float4*>(Kg + (size_t)(kv0 + r) * HEADDIM + cv);
            Ks[r][cv + 0] = kv.x; Ks[r][cv + 1] = kv.y;
            Ks[r][cv + 2] = kv.z; Ks[r][cv + 3] = kv.w;
            float4 vv = *reinterpret_cast<const float4*>(Vg + (size_t)(kv0 + r) * HEADDIM + cv);
            Vs[r][cv + 0] = __uint_as_float(f2tf32(vv.x));
            Vs[r][cv + 1] = __uint_as_float(f2tf32(vv.y));
            Vs[r][cv + 2] = __uint_as_float(f2tf32(vv.z));
            Vs[r][cv + 3] = __uint_as_float(f2tf32(vv.w));
        }
        __syncthreads();

#pragma unroll
        for (int i = 0; i < 16; i++) {
            int r = (tid >> 5) + i * 4;
            float sn, cs;
            sincosf((float)(kv0 + r) * invf, &sn, &cs);
            float x1 = Ks[r][jr], x2 = Ks[r][jr + 32];
            Ks[r][jr]      = __uint_as_float(f2tf32(x1 * cs - x2 * sn));
            Ks[r][jr + 32] = __uint_as_float(f2tf32(x2 * cs + x1 * sn));
        }
        __syncthreads();

        float s[2][8][4];
#pragma unroll
        for (int t = 0; t < 2; t++)
#pragma unroll
            for (int n = 0; n < 8; n++)
#pragma unroll
                for (int c = 0; c < 4; c++) s[t][n][c] = 0.0f;

#pragma unroll
        for (int n = 0; n < 8; n++) {
#pragma unroll
            for (int kc = 0; kc < 8; kc++) {
                uint32_t b0 = __float_as_uint(Ks[n * 8 + g][kc * 8 + q]);
                uint32_t b1 = __float_as_uint(Ks[n * 8 + g][kc * 8 + q + 4]);
                mma_tf32(s[0][n], aq[0][kc], b0, b1);
                mma_tf32(s[1][n], aq[1][kc], b0, b1);
            }
        }

#pragma unroll
        for (int t = 0; t < 2; t++) {
            float mxA = -1e30f, mxB = -1e30f;
#pragma unroll
            for (int n = 0; n < 8; n++) {
                mxA = fmaxf(mxA, fmaxf(s[t][n][0], s[t][n][1]));
                mxB = fmaxf(mxB, fmaxf(s[t][n][2], s[t][n][3]));
            }
            mxA = fmaxf(mxA, __shfl_xor_sync(0xffffffffu, mxA, 1));
            mxA = fmaxf(mxA, __shfl_xor_sync(0xffffffffu, mxA, 2));
            mxB = fmaxf(mxB, __shfl_xor_sync(0xffffffffu, mxB, 1));
            mxB = fmaxf(mxB, __shfl_xor_sync(0xffffffffu, mxB, 2));
            float mnA = fmaxf(mA[t], mxA);
            float mnB = fmaxf(mB[t], mxB);
            float cA = __expf(mA[t] - mnA);
            float cB = __expf(mB[t] - mnB);
            float rsA = 0.0f, rsB = 0.0f;
#pragma unroll
            for (int n = 0; n < 8; n++) {
                s[t][n][0] = __expf(s[t][n][0] - mnA); rsA += s[t][n][0];
                s[t][n][1] = __expf(s[t][n][1] - mnA); rsA += s[t][n][1];
                s[t][n][2] = __expf(s[t][n][2] - mnB); rsB += s[t][n][2];
                s[t][n][3] = __expf(s[t][n][3] - mnB); rsB += s[t][n][3];
                o[t][n][0] *= cA; o[t][n][1] *= cA;
                o[t][n][2] *= cB; o[t][n][3] *= cB;
            }
            rsA += __shfl_xor_sync(0xffffffffu, rsA, 1);
            rsA += __shfl_xor_sync(0xffffffffu, rsA, 2);
            rsB += __shfl_xor_sync(0xffffffffu, rsB, 1);
            rsB += __shfl_xor_sync(0xffffffffu, rsB, 2);
            lA[t] = lA[t] * cA + rsA; mA[t] = mnA;
            lB[t] = lB[t] * cB + rsB; mB[t] = mnB;
        }

        const int src0 = (g << 2) + (q >> 1);
        const int src1 = src0 + 2;
        const bool odd = (q & 1);
#pragma unroll
        for (int kc = 0; kc < 8; kc++) {
            uint32_t ap[2][4];
#pragma unroll
            for (int t = 0; t < 2; t++) {
                float v00 = __shfl_sync(0xffffffffu, s[t][kc][0], src0);
                float v01 = __shfl_sync(0xffffffffu, s[t][kc][1], src0);
                float v02 = __shfl_sync(0xffffffffu, s[t][kc][2], src0);
                float v03 = __shfl_sync(0xffffffffu, s[t][kc][3], src0);
                float v10 = __shfl_sync(0xffffffffu, s[t][kc][0], src1);
                float v11 = __shfl_sync(0xffffffffu, s[t][kc][1], src1);
                float v12 = __shfl_sync(0xffffffffu, s[t][kc][2], src1);
                float v13 = __shfl_sync(0xffffffffu, s[t][kc][3], src1);
                ap[t][0] = f2tf32(odd ? v01 : v00);
                ap[t][1] = f2tf32(odd ? v03 : v02);
                ap[t][2] = f2tf32(odd ? v11 : v10);
                ap[t][3] = f2tf32(odd ? v13 : v12);
            }
#pragma unroll
            for (int n = 0; n < 8; n++) {
                uint32_t b0 = __float_as_uint(Vs[kc * 8 + q][n * 8 + g]);
                uint32_t b1 = __float_as_uint(Vs[kc * 8 + q + 4][n * 8 + g]);
                mma_tf32(o[0][n], ap[0], b0, b1);
                mma_tf32(o[1][n], ap[1], b0, b1);
            }
        }
    }

#pragma unroll
    for (int t = 0; t < 2; t++) {
        float iA = 1.0f / lA[t];
        float iB = 1.0f / lB[t];
        int row0 = q0 + w * 32 + t * 16 + g;
#pragma unroll
        for (int n = 0; n < 8; n++) {
            int col = n * 8 + 2 * q;
            float2 r0v = make_float2(o[t][n][0] * iA, o[t][n][1] * iA);
            float2 r1v = make_float2(o[t][n][2] * iB, o[t][n][3] * iB);
            *reinterpret_cast<float2*>(
                g_attn + ((size_t)(b_ * SEQLEN + row0) * NHEAD + h_) * HEADDIM + col) = r0v;
            *reinterpret_cast<float2*>(
                g_attn + ((size_t)(b_ * SEQLEN + row0 + 8) * NHEAD + h_) * HEADDIM + col) = r1v;
        }
    }
}

// ---------------------------------------------------------------------------
extern "C" void kernel_launch(void* const* d_in, const int* in_sizes, int n_in,
                              void* d_out, int out_size)
{
    const float* x  = (const float*)d_in[0];
    const float* Wq = (const float*)d_in[1];
    const float* bq = (const float*)d_in[2];
    const float* Wk = (const float*)d_in[3];
    const float* bk = (const float*)d_in[4];
    const float* Wv = (const float*)d_in[5];
    const float* bv = (const float*)d_in[6];
    const float* Wo = (const float*)d_in[7];
    const float* bo = (const float*)d_in[8];
    float* out = (float*)d_out;

    dim3 ggrid(DMODEL / 128, MROWS / 128);   // (8, 64)
    gemm_tf32<<<ggrid, 256>>>(x, Wq, bq, nullptr, 0);
    gemm_tf32<<<ggrid, 256>>>(x, Wk, bk, nullptr, 1);
    gemm_tf32<<<ggrid, 256>>>(x, Wv, bv, nullptr, 2);

    attn_mma_kernel<<<dim3(SEQLEN / 128, BATCH * NHEAD), 128>>>();

    gemm_tf32<<<ggrid, 256>>>(nullptr, Wo, bo, out, 3);
}

// round 6
// speedup vs baseline: 5.6792x; 1.1590x over previous
#include <cuda_runtime.h>
#include <math.h>
#include <stdint.h>

// Problem constants
#define BATCH   4
#define SEQLEN  2048
#define DMODEL  1024
#define NHEAD   16
#define HEADDIM 64
#define MROWS   (BATCH * SEQLEN)   // 8192

// Scratch (device globals: no allocation allowed in kernel_launch)
__device__ float g_q[(size_t)BATCH * NHEAD * SEQLEN * HEADDIM];    // [B,H,L,hd]
__device__ float g_k[(size_t)BATCH * NHEAD * SEQLEN * HEADDIM];
__device__ float g_v[(size_t)BATCH * NHEAD * SEQLEN * HEADDIM];
__device__ float g_attn[(size_t)MROWS * DMODEL];                   // [B,L,H*hd]

// ---------------------------------------------------------------------------
// TF32 mma helpers
// ---------------------------------------------------------------------------
__device__ __forceinline__ uint32_t f2tf32(float f) {
    uint32_t u;
    asm("cvt.rna.tf32.f32 %0, %1;" : "=r"(u) : "f"(f));
    return u;
}

__device__ __forceinline__ void mma_tf32(float* d, const uint32_t* a,
                                         uint32_t b0, uint32_t b1) {
    asm volatile(
        "mma.sync.aligned.m16n8k8.row.col.f32.tf32.tf32.f32 "
        "{%0,%1,%2,%3}, {%4,%5,%6,%7}, {%8,%9}, {%0,%1,%2,%3};\n"
        : "+f"(d[0]), "+f"(d[1]), "+f"(d[2]), "+f"(d[3])
        : "r"(a[0]), "r"(a[1]), "r"(a[2]), "r"(a[3]), "r"(b0), "r"(b1));
}

// ---------------------------------------------------------------------------
// TF32 tensor-core GEMM (unchanged from round 5)
// ---------------------------------------------------------------------------
__global__ __launch_bounds__(256) void gemm_tf32(const float* __restrict__ A_in,
                                                 const float* __restrict__ W,
                                                 const float* __restrict__ bias,
                                                 float* __restrict__ C_out,
                                                 int sel)
{
    __shared__ float As[128][36];
    __shared__ float Ws[128][36];

    const int K = DMODEL;
    const float* A = (sel == 3) ? g_attn : A_in;
    float* C;
    if (sel == 0)      C = g_q;
    else if (sel == 1) C = g_k;
    else if (sel == 2) C = g_v;
    else               C = C_out;

    const int tid  = threadIdx.x;
    const int w    = tid >> 5;
    const int lane = tid & 31;
    const int g    = lane >> 2;
    const int q    = lane & 3;
    const int wm   = (w & 1) * 64;
    const int wn   = (w >> 1) * 32;

    const int m0 = blockIdx.y * 128;
    const int n0 = blockIdx.x * 128;

    const float* Aptr = A + (size_t)m0 * K;
    const float* Wptr = W + (size_t)n0 * K;

    int ld_row[4], ld_c4[4];
#pragma unroll
    for (int i = 0; i < 4; i++) {
        int idx = tid + i * 256;
        ld_row[i] = idx >> 3;
        ld_c4[i]  = (idx & 7) * 4;
    }

    float acc[4][4][4];
#pragma unroll
    for (int mi = 0; mi < 4; mi++)
#pragma unroll
        for (int nj = 0; nj < 4; nj++)
#pragma unroll
            for (int c = 0; c < 4; c++) acc[mi][nj][c] = 0.0f;

    float4 pa[4], pw[4];
#pragma unroll
    for (int i = 0; i < 4; i++) {
        pa[i] = *reinterpret_cast<const float4*>(Aptr + (size_t)ld_row[i] * K + ld_c4[i]);
        pw[i] = *reinterpret_cast<const float4*>(Wptr + (size_t)ld_row[i] * K + ld_c4[i]);
    }

    for (int kt = 0; kt < K; kt += 32) {
#pragma unroll
        for (int i = 0; i < 4; i++) {
            float4 a = pa[i];
            float4 t;
            t.x = __uint_as_float(f2tf32(a.x));
            t.y = __uint_as_float(f2tf32(a.y));
            t.z = __uint_as_float(f2tf32(a.z));
            t.w = __uint_as_float(f2tf32(a.w));
            *reinterpret_cast<float4*>(&As[ld_row[i]][ld_c4[i]]) = t;
            float4 b = pw[i];
            t.x = __uint_as_float(f2tf32(b.x));
            t.y = __uint_as_float(f2tf32(b.y));
            t.z = __uint_as_float(f2tf32(b.z));
            t.w = __uint_as_float(f2tf32(b.w));
            *reinterpret_cast<float4*>(&Ws[ld_row[i]][ld_c4[i]]) = t;
        }
        __syncthreads();

        if (kt + 32 < K) {
#pragma unroll
            for (int i = 0; i < 4; i++) {
                pa[i] = *reinterpret_cast<const float4*>(
                    Aptr + (size_t)ld_row[i] * K + kt + 32 + ld_c4[i]);
                pw[i] = *reinterpret_cast<const float4*>(
                    Wptr + (size_t)ld_row[i] * K + kt + 32 + ld_c4[i]);
            }
        }

#pragma unroll
        for (int kc = 0; kc < 4; kc++) {
            const int k0 = kc * 8;
            uint32_t a[4][4];
#pragma unroll
            for (int mi = 0; mi < 4; mi++) {
                int r = wm + mi * 16;
                a[mi][0] = __float_as_uint(As[r + g][k0 + q]);
                a[mi][1] = __float_as_uint(As[r + 8 + g][k0 + q]);
                a[mi][2] = __float_as_uint(As[r + g][k0 + q + 4]);
                a[mi][3] = __float_as_uint(As[r + 8 + g][k0 + q + 4]);
            }
            uint32_t b[4][2];
#pragma unroll
            for (int nj = 0; nj < 4; nj++) {
                int bn = wn + nj * 8;
                b[nj][0] = __float_as_uint(Ws[bn + g][k0 + q]);
                b[nj][1] = __float_as_uint(Ws[bn + g][k0 + q + 4]);
            }
#pragma unroll
            for (int mi = 0; mi < 4; mi++)
#pragma unroll
                for (int nj = 0; nj < 4; nj++)
                    mma_tf32(acc[mi][nj], a[mi], b[nj][0], b[nj][1]);
        }
        __syncthreads();
    }

#pragma unroll
    for (int nj = 0; nj < 4; nj++) {
        int cn = n0 + wn + nj * 8 + 2 * q;
        float b0 = bias[cn];
        float b1 = bias[cn + 1];
#pragma unroll
        for (int mi = 0; mi < 4; mi++) {
            int mr0 = m0 + wm + mi * 16 + g;
            int mr1 = mr0 + 8;
            float2 v0 = make_float2(acc[mi][nj][0] + b0, acc[mi][nj][1] + b1);
            float2 v1 = make_float2(acc[mi][nj][2] + b0, acc[mi][nj][3] + b1);
            if (sel <= 2) {
                int h_ = cn >> 6;
                int d_ = cn & 63;
                int b0_ = mr0 >> 11, l0_ = mr0 & 2047;
                int b1_ = mr1 >> 11, l1_ = mr1 & 2047;
                *reinterpret_cast<float2*>(
                    C + (((size_t)(b0_ * NHEAD + h_)) * SEQLEN + l0_) * HEADDIM + d_) = v0;
                *reinterpret_cast<float2*>(
                    C + (((size_t)(b1_ * NHEAD + h_)) * SEQLEN + l1_) * HEADDIM + d_) = v1;
            } else {
                *reinterpret_cast<float2*>(C + (size_t)mr0 * DMODEL + cn) = v0;
                *reinterpret_cast<float2*>(C + (size_t)mr1 * DMODEL + cn) = v1;
            }
        }
    }
}

// ---------------------------------------------------------------------------
// RoPE pre-pass: rotate g_q (with 1/8 softmax scale folded) and g_k in place.
// One thread per (bh, l, d-pair). Layout [B,H,L,64].
// ---------------------------------------------------------------------------
__global__ __launch_bounds__(256) void rope_kernel()
{
    int idx = blockIdx.x * 256 + threadIdx.x;      // 0 .. 4M-1
    int d  = idx & 31;
    int l  = (idx >> 5) & (SEQLEN - 1);
    int bh = idx >> 16;                             // 0..63
    size_t base = ((size_t)bh * SEQLEN + l) * HEADDIM;

    float invf = __expf(-(float)d * (9.210340371976184f / 32.0f));
    float sn, cs;
    sincosf((float)l * invf, &sn, &cs);

    float q1 = g_q[base + d], q2 = g_q[base + d + 32];
    g_q[base + d]      = (q1 * cs - q2 * sn) * 0.125f;
    g_q[base + d + 32] = (q2 * cs + q1 * sn) * 0.125f;

    float k1 = g_k[base + d], k2 = g_k[base + d + 32];
    g_k[base + d]      = k1 * cs - k2 * sn;
    g_k[base + d + 32] = k2 * cs + k1 * sn;
}

// ---------------------------------------------------------------------------
// Flash attention, tf32 mma, RoPE precomputed.
// Grid: (L/128, B*H). Block: 256 threads (8 warps), warp w owns q-rows
// [w*16, w*16+16): one m16 fragment. kv tiles of 64.
// ---------------------------------------------------------------------------
__global__ __launch_bounds__(256, 2) void attn_mma_kernel()
{
    __shared__ float smem_all[64 * 68 + 64 * 72];   // 35840 B
    float (*Ks)[68] = (float(*)[68])smem_all;
    float (*Vs)[72] = (float(*)[72])(smem_all + 64 * 68);
    float (*Qs)[68] = (float(*)[68])smem_all;       // 128*68 = 8704 <= 8960

    const int tid  = threadIdx.x;
    const int w    = tid >> 5;
    const int lane = tid & 31;
    const int g    = lane >> 2;
    const int q    = lane & 3;

    const int bh = blockIdx.y;
    const int b_ = bh >> 4;
    const int h_ = bh & 15;
    const int q0 = blockIdx.x * 128;

    const float* Qg = g_q + (size_t)bh * SEQLEN * HEADDIM;
    const float* Kg = g_k + (size_t)bh * SEQLEN * HEADDIM;
    const float* Vg = g_v + (size_t)bh * SEQLEN * HEADDIM;

    // ---- Load Q tile [128][64] (already RoPE'd + scaled) ----
#pragma unroll
    for (int i = 0; i < 8; i++) {
        int idx = tid + i * 256;
        int r = idx >> 4;
        int cv = (idx & 15) * 4;
        float4 v = *reinterpret_cast<const float4*>(Qg + (size_t)(q0 + r) * HEADDIM + cv);
        Qs[r][cv + 0] = v.x; Qs[r][cv + 1] = v.y;
        Qs[r][cv + 2] = v.z; Qs[r][cv + 3] = v.w;
    }
    __syncthreads();

    // ---- Extract Q A-fragment (1 m-frag per warp, persists in registers) ----
    uint32_t aq[8][4];
    {
        int row0 = w * 16 + g;
#pragma unroll
        for (int kc = 0; kc < 8; kc++) {
            int c0 = kc * 8 + q;
            aq[kc][0] = f2tf32(Qs[row0][c0]);
            aq[kc][1] = f2tf32(Qs[row0 + 8][c0]);
            aq[kc][2] = f2tf32(Qs[row0][c0 + 4]);
            aq[kc][3] = f2tf32(Qs[row0 + 8][c0 + 4]);
        }
    }

    float o[8][4];
    float mA = -INFINITY, mB = -INFINITY, lA = 0.0f, lB = 0.0f;
#pragma unroll
    for (int n = 0; n < 8; n++)
#pragma unroll
        for (int c = 0; c < 4; c++) o[n][c] = 0.0f;

    for (int kk = 0; kk < 32; kk++) {
        const int kv0 = kk * 64;
        __syncthreads();   // kk=0: Q frags extracted; kk>0: prior mma reads done

        // ---- Load K and V tiles (tf32-converted at store) ----
#pragma unroll
        for (int i = 0; i < 4; i++) {
            int idx = tid + i * 256;
            int r = idx >> 4;
            int cv = (idx & 15) * 4;
            float4 kv = *reinterpret_cast<const float4*>(Kg + (size_t)(kv0 + r) * HEADDIM + cv);
            Ks[r][cv + 0] = __uint_as_float(f2tf32(kv.x));
            Ks[r][cv + 1] = __uint_as_float(f2tf32(kv.y));
            Ks[r][cv + 2] = __uint_as_float(f2tf32(kv.z));
            Ks[r][cv + 3] = __uint_as_float(f2tf32(kv.w));
            float4 vv = *reinterpret_cast<const float4*>(Vg + (size_t)(kv0 + r) * HEADDIM + cv);
            Vs[r][cv + 0] = __uint_as_float(f2tf32(vv.x));
            Vs[r][cv + 1] = __uint_as_float(f2tf32(vv.y));
            Vs[r][cv + 2] = __uint_as_float(f2tf32(vv.z));
            Vs[r][cv + 3] = __uint_as_float(f2tf32(vv.w));
        }
        __syncthreads();

        // ---- S = Q . K^T  (m16n8k8 tf32) ----
        float s[8][4];
#pragma unroll
        for (int n = 0; n < 8; n++)
#pragma unroll
            for (int c = 0; c < 4; c++) s[n][c] = 0.0f;

#pragma unroll
        for (int n = 0; n < 8; n++) {
#pragma unroll
            for (int kc = 0; kc < 8; kc++) {
                uint32_t b0 = __float_as_uint(Ks[n * 8 + g][kc * 8 + q]);
                uint32_t b1 = __float_as_uint(Ks[n * 8 + g][kc * 8 + q + 4]);
                mma_tf32(s[n], aq[kc], b0, b1);
            }
        }

        // ---- Online softmax (rows g -> c0,c1 ; g+8 -> c2,c3) ----
        {
            float mxA = -1e30f, mxB = -1e30f;
#pragma unroll
            for (int n = 0; n < 8; n++) {
                mxA = fmaxf(mxA, fmaxf(s[n][0], s[n][1]));
                mxB = fmaxf(mxB, fmaxf(s[n][2], s[n][3]));
            }
            mxA = fmaxf(mxA, __shfl_xor_sync(0xffffffffu, mxA, 1));
            mxA = fmaxf(mxA, __shfl_xor_sync(0xffffffffu, mxA, 2));
            mxB = fmaxf(mxB, __shfl_xor_sync(0xffffffffu, mxB, 1));
            mxB = fmaxf(mxB, __shfl_xor_sync(0xffffffffu, mxB, 2));
            float mnA = fmaxf(mA, mxA);
            float mnB = fmaxf(mB, mxB);
            float cA = __expf(mA - mnA);
            float cB = __expf(mB - mnB);
            float rsA = 0.0f, rsB = 0.0f;
#pragma unroll
            for (int n = 0; n < 8; n++) {
                s[n][0] = __expf(s[n][0] - mnA); rsA += s[n][0];
                s[n][1] = __expf(s[n][1] - mnA); rsA += s[n][1];
                s[n][2] = __expf(s[n][2] - mnB); rsB += s[n][2];
                s[n][3] = __expf(s[n][3] - mnB); rsB += s[n][3];
                o[n][0] *= cA; o[n][1] *= cA;
                o[n][2] *= cB; o[n][3] *= cB;
            }
            rsA += __shfl_xor_sync(0xffffffffu, rsA, 1);
            rsA += __shfl_xor_sync(0xffffffffu, rsA, 2);
            rsB += __shfl_xor_sync(0xffffffffu, rsB, 1);
            rsB += __shfl_xor_sync(0xffffffffu, rsB, 2);
            lA = lA * cA + rsA; mA = mnA;
            lB = lB * cB + rsB; mB = mnB;
        }

        // ---- O += P . V : build P A-frags from S accum layout via shfl ----
        const int src0 = (g << 2) + (q >> 1);
        const int src1 = src0 + 2;
        const bool odd = (q & 1);
#pragma unroll
        for (int kc = 0; kc < 8; kc++) {
            uint32_t ap[4];
            float v00 = __shfl_sync(0xffffffffu, s[kc][0], src0);
            float v01 = __shfl_sync(0xffffffffu, s[kc][1], src0);
            float v02 = __shfl_sync(0xffffffffu, s[kc][2], src0);
            float v03 = __shfl_sync(0xffffffffu, s[kc][3], src0);
            float v10 = __shfl_sync(0xffffffffu, s[kc][0], src1);
            float v11 = __shfl_sync(0xffffffffu, s[kc][1], src1);
            float v12 = __shfl_sync(0xffffffffu, s[kc][2], src1);
            float v13 = __shfl_sync(0xffffffffu, s[kc][3], src1);
            ap[0] = f2tf32(odd ? v01 : v00);
            ap[1] = f2tf32(odd ? v03 : v02);
            ap[2] = f2tf32(odd ? v11 : v10);
            ap[3] = f2tf32(odd ? v13 : v12);
#pragma unroll
            for (int n = 0; n < 8; n++) {
                uint32_t b0 = __float_as_uint(Vs[kc * 8 + q][n * 8 + g]);
                uint32_t b1 = __float_as_uint(Vs[kc * 8 + q + 4][n * 8 + g]);
                mma_tf32(o[n], ap, b0, b1);
            }
        }
    }

    // ---- Epilogue: normalize, write [B,L,H*hd] ----
    {
        float iA = 1.0f / lA;
        float iB = 1.0f / lB;
        int row0 = q0 + w * 16 + g;
#pragma unroll
        for (int n = 0; n < 8; n++) {
            int col = n * 8 + 2 * q;
            float2 r0v = make_float2(o[n][0] * iA, o[n][1] * iA);
            float2 r1v = make_float2(o[n][2] * iB, o[n][3] * iB);
            *reinterpret_cast<float2*>(
                g_attn + ((size_t)(b_ * SEQLEN + row0) * NHEAD + h_) * HEADDIM + col) = r0v;
            *reinterpret_cast<float2*>(
                g_attn + ((size_t)(b_ * SEQLEN + row0 + 8) * NHEAD + h_) * HEADDIM + col) = r1v;
        }
    }
}

// ---------------------------------------------------------------------------
extern "C" void kernel_launch(void* const* d_in, const int* in_sizes, int n_in,
                              void* d_out, int out_size)
{
    const float* x  = (const float*)d_in[0];
    const float* Wq = (const float*)d_in[1];
    const float* bq = (const float*)d_in[2];
    const float* Wk = (const float*)d_in[3];
    const float* bk = (const float*)d_in[4];
    const float* Wv = (const float*)d_in[5];
    const float* bv = (const float*)d_in[6];
    const float* Wo = (const float*)d_in[7];
    const float* bo = (const float*)d_in[8];
    float* out = (float*)d_out;

    dim3 ggrid(DMODEL / 128, MROWS / 128);   // (8, 64)
    gemm_tf32<<<ggrid, 256>>>(x, Wq, bq, nullptr, 0);
    gemm_tf32<<<ggrid, 256>>>(x, Wk, bk, nullptr, 1);
    gemm_tf32<<<ggrid, 256>>>(x, Wv, bv, nullptr, 2);

    rope_kernel<<<(BATCH * NHEAD * SEQLEN * 32) / 256, 256>>>();

    attn_mma_kernel<<<dim3(SEQLEN / 128, BATCH * NHEAD), 256>>>();

    gemm_tf32<<<ggrid, 256>>>(nullptr, Wo, bo, out, 3);
}